// round 3
// baseline (speedup 1.0000x reference)
#include <cuda_runtime.h>

// ---------------- problem constants ----------------
#define HW      4096
#define NPIX    (HW*HW)
#define NPATCH  64
#define K1      31458u   // loop1 continues iff count(v>th) <= 31457  <=>  v_(31458) <= th
#define K2      20972u   // loop2 continues iff count(v>th) >= 20972  <=>  v_(20972) >  th
#define LOKEY   0x3D800000u
#define HIKEY   0x3F800000u
#define CB_SHIFT 12
#define NCOARSE 8192
#define NSUB    4096

// ---------------- device scratch ----------------
__device__ float        g_blur[NPIX];
__device__ unsigned int g_hist[NPATCH][NCOARSE + 2];   // +under, +over
__device__ unsigned int g_sub [NPATCH][2][NSUB];
__device__ unsigned int g_sel [NPATCH][4];             // bin1, above1, bin2, above2
__device__ unsigned int g_key [NPATCH][2];
__device__ float        g_th  [NPATCH];

// ---------------- K0: zero histograms ----------------
__global__ void zero_k() {
    int i = blockIdx.x * 256 + threadIdx.x;
    if (i < NPATCH * (NCOARSE + 2)) ((unsigned int*)g_hist)[i] = 0u;
    if (i < NPATCH * 2 * NSUB)      ((unsigned int*)g_sub)[i]  = 0u;
}

// ---------------- K1: blur (4 px/thread, float4 loads) + global RED histogram ----------------
// Tap chain per pixel IDENTICAL to passing version: kw outer, kh inner, single fmaf chain.
__global__ __launch_bounds__(256) void blur_hist(const float* __restrict__ x,
                                                 const float* __restrict__ bk) {
    const float w  = bk[0];
    const int   c0 = (blockIdx.x * 256 + threadIdx.x) * 4;  // first of 4 columns
    const int   y0 = blockIdx.y * 32;
    const int   pcol = c0 >> 9;
    const bool  safe = (c0 >= 4) && (c0 <= HW - 9);          // need cols c0-4 .. c0+7

    for (int y = y0; y < y0 + 32; y++) {
        float f[5][12];
        #pragma unroll
        for (int i = 0; i < 5; i++) {
            int yy = y - 2 + i;
            if (yy < 0 || yy >= HW) {
                #pragma unroll
                for (int j = 0; j < 12; j++) f[i][j] = 0.0f;
            } else if (safe) {
                const float4* p = (const float4*)&x[yy * HW + c0 - 4];
                float4 a = __ldg(p), b = __ldg(p + 1), c = __ldg(p + 2);
                f[i][0]=a.x; f[i][1]=a.y; f[i][2]=a.z;  f[i][3]=a.w;
                f[i][4]=b.x; f[i][5]=b.y; f[i][6]=b.z;  f[i][7]=b.w;
                f[i][8]=c.x; f[i][9]=c.y; f[i][10]=c.z; f[i][11]=c.w;
            } else {
                #pragma unroll
                for (int j = 0; j < 12; j++) {
                    int cc = c0 - 4 + j;
                    f[i][j] = (cc >= 0 && cc < HW) ? __ldg(&x[yy * HW + cc]) : 0.0f;
                }
            }
        }
        float4 o;
        float* op = (float*)&o;
        unsigned int* gh = g_hist[((y >> 9) << 3) + pcol];
        #pragma unroll
        for (int u = 0; u < 4; u++) {
            float acc = 0.0f;
            #pragma unroll
            for (int j = 0; j < 5; j++)        // kw outer
                #pragma unroll
                for (int i = 0; i < 5; i++)    // kh inner (fastest) — Eigen order
                    acc = fmaf(f[i][u + j + 2], w, acc);
            op[u] = acc;
            unsigned int key = __float_as_uint(acc);
            unsigned int b = (key < LOKEY) ? NCOARSE
                           : (key >= HIKEY) ? (NCOARSE + 1)
                           : ((key - LOKEY) >> CB_SHIFT);
            atomicAdd(&gh[b], 1u);             // no return -> RED at L2
        }
        *(float4*)&g_blur[y * HW + c0] = o;
    }
}

// ---------------- K2: pick coarse bin containing v_(K1), v_(K2) per patch ----------------
__global__ __launch_bounds__(1024) void coarse_select() {
    __shared__ unsigned int ss[1024];
    const int p = blockIdx.x, t = threadIdx.x;
    const unsigned int* cnt = g_hist[p];

    unsigned int c[8], s = 0;
    #pragma unroll
    for (int j = 0; j < 8; j++) { c[j] = cnt[t * 8 + j]; s += c[j]; }
    ss[t] = s;
    __syncthreads();
    for (int off = 1; off < 1024; off <<= 1) {   // inclusive suffix scan
        unsigned int v = (t + off < 1024) ? ss[t + off] : 0u;
        __syncthreads();
        ss[t] += v;
        __syncthreads();
    }
    const unsigned int over = cnt[NCOARSE + 1];
    unsigned int above = ((t < 1023) ? ss[t + 1] : 0u) + over;

    if (t == 0) { g_sel[p][0] = 0u; g_sel[p][1] = K1 - 1u;
                  g_sel[p][2] = 0u; g_sel[p][3] = K2 - 1u; }
    __syncthreads();

    unsigned int a = above;
    #pragma unroll
    for (int j = 7; j >= 0; j--) {
        unsigned int b = (unsigned int)(t * 8 + j);
        unsigned int cb = c[j];
        if (a < K1 && K1 <= a + cb) { g_sel[p][0] = b; g_sel[p][1] = a; }
        if (a < K2 && K2 <= a + cb) { g_sel[p][2] = b; g_sel[p][3] = a; }
        a += cb;
    }
}

// ---------------- K3a: sub-histogram, 16 slices per patch (1024 CTAs) ----------------
__global__ __launch_bounds__(256) void refine_hist() {
    const int p = blockIdx.x >> 4;
    const int s = blockIdx.x & 15;
    const unsigned int bin1 = g_sel[p][0], bin2 = g_sel[p][2];
    const int pr = p >> 3, pc = p & 7;
    const float* base = g_blur + (pr * 512 + s * 32) * HW + pc * 512;
    for (int i = threadIdx.x; i < 32 * 512; i += 256) {
        int ly = i >> 9, lx = i & 511;
        unsigned int key = __float_as_uint(base[ly * HW + lx]);
        if (key >= LOKEY && key < HIKEY) {
            unsigned int cb = (key - LOKEY) >> CB_SHIFT;
            if (cb == bin1) atomicAdd(&g_sub[p][0][key & (NSUB - 1)], 1u);
            if (cb == bin2) atomicAdd(&g_sub[p][1][key & (NSUB - 1)], 1u);
        }
    }
}

// ---------------- K3b: select exact float-bit key within the coarse bin ----------------
__global__ __launch_bounds__(1024) void refine_select() {
    __shared__ unsigned int ss[1024];
    const int p = blockIdx.x, t = threadIdx.x;

    for (int q = 0; q < 2; q++) {
        const unsigned int bin = g_sel[p][q * 2];
        const unsigned int ab  = g_sel[p][q * 2 + 1];
        const unsigned int r   = (q ? K2 : K1) - ab;

        unsigned int c[4], s = 0;
        #pragma unroll
        for (int j = 0; j < 4; j++) { c[j] = g_sub[p][q][t * 4 + j]; s += c[j]; }
        ss[t] = s;
        __syncthreads();
        for (int off = 1; off < 1024; off <<= 1) {
            unsigned int v = (t + off < 1024) ? ss[t + off] : 0u;
            __syncthreads();
            ss[t] += v;
            __syncthreads();
        }
        unsigned int above = (t < 1023) ? ss[t + 1] : 0u;
        if (t == 0) g_key[p][q] = LOKEY + (bin << CB_SHIFT);
        __syncthreads();
        unsigned int a = above;
        #pragma unroll
        for (int j = 3; j >= 0; j--) {
            unsigned int idx = (unsigned int)(t * 4 + j);
            if (a < r && r <= a + c[j])
                g_key[p][q] = LOKEY + (bin << CB_SHIFT) + idx;
            a += c[j];
        }
        __syncthreads();
    }
}

// ---------------- K4: sequential threshold walk (bit-faithful) ----------------
__global__ void walk() {
    if (blockIdx.x == 0 && threadIdx.x == 0) {
        float th = 0.5f;
        for (int p = 0; p < NPATCH; p++) {
            float A = __uint_as_float(g_key[p][0]);
            float B = __uint_as_float(g_key[p][1]);
            int g = 0;
            while (A <= th && g < 200000) { th -= 0.0005f; g++; }
            g = 0;
            while (B >  th && g < 200000) { th += 0.0005f; g++; }
            g_th[p] = th;
        }
    }
}

// ---------------- K5: bit-packed binarize + close (dilate5, erode5) ----------------
#define CTW  256   // tile output cols
#define CTH  128   // tile output rows
#define WPR  10    // 8 center words + 1 halo word each side
#define TROWS 136  // 128 + 4 halo each side
__global__ __launch_bounds__(256) void close_k(float* __restrict__ out) {
    __shared__ unsigned int A[TROWS][WPR];
    __shared__ unsigned int B[TROWS][WPR];
    __shared__ float sth[NPATCH];
    const int t = threadIdx.x;
    if (t < NPATCH) sth[t] = g_th[t];
    __syncthreads();

    const int gx0 = blockIdx.x * CTW;
    const int gy0 = blockIdx.y * CTH;
    const int lane = t & 31, wid = t >> 5;

    // binarize -> packed words via ballot (out-of-image = 0: correct for dilate)
    for (int idx = wid; idx < TROWS * WPR; idx += 8) {
        int r = idx / WPR, wc = idx % WPR;
        int gy = gy0 + r - 4;
        int gx = gx0 + (wc - 1) * 32 + lane;
        unsigned int bit = 0;
        if ((unsigned)gy < HW && (unsigned)gx < HW) {
            float bl = g_blur[gy * HW + gx];
            bit = (bl > sth[((gy >> 9) << 3) + (gx >> 9)]) ? 1u : 0u;
        }
        unsigned int word = __ballot_sync(0xffffffffu, bit);
        if (lane == 0) A[r][wc] = word;
    }
    __syncthreads();

    // horizontal dilate (OR, radius 2)
    for (int i = t; i < TROWS * WPR; i += 256) {
        int r = i / WPR, wc = i % WPR;
        unsigned int wv = A[r][wc];
        unsigned int lw = wc > 0       ? A[r][wc - 1] : 0u;
        unsigned int rw = wc < WPR - 1 ? A[r][wc + 1] : 0u;
        B[r][wc] = wv | __funnelshift_r(wv, rw, 1) | __funnelshift_r(wv, rw, 2)
                      | __funnelshift_l(lw, wv, 1) | __funnelshift_l(lw, wv, 2);
    }
    __syncthreads();

    // vertical dilate (OR) + out-of-image mask (-> 1, identity for the following erode)
    for (int i = t; i < TROWS * WPR; i += 256) {
        int r = i / WPR, wc = i % WPR;
        unsigned int d = 0u;
        if (r >= 2 && r < TROWS - 2)
            d = B[r-2][wc] | B[r-1][wc] | B[r][wc] | B[r+1][wc] | B[r+2][wc];
        int gy = gy0 + r - 4;
        bool xout = (wc == 0 && gx0 == 0) || (wc == WPR - 1 && gx0 + CTW == HW);
        if ((unsigned)gy >= HW || xout) d = 0xffffffffu;
        A[r][wc] = d;
    }
    __syncthreads();

    // horizontal erode (AND, radius 2)
    for (int i = t; i < TROWS * WPR; i += 256) {
        int r = i / WPR, wc = i % WPR;
        unsigned int wv = A[r][wc];
        unsigned int lw = wc > 0       ? A[r][wc - 1] : 0xffffffffu;
        unsigned int rw = wc < WPR - 1 ? A[r][wc + 1] : 0xffffffffu;
        B[r][wc] = wv & __funnelshift_r(wv, rw, 1) & __funnelshift_r(wv, rw, 2)
                      & __funnelshift_l(lw, wv, 1) & __funnelshift_l(lw, wv, 2);
    }
    __syncthreads();

    // vertical erode + unpack to float + store (center 128 rows x 8 words)
    for (int i = t; i < CTH * 8; i += 256) {
        int r = (i >> 3) + 4, wc = (i & 7) + 1;
        unsigned int v = B[r-2][wc] & B[r-1][wc] & B[r][wc] & B[r+1][wc] & B[r+2][wc];
        int gy = gy0 + r - 4;
        int gx = gx0 + (wc - 1) * 32;
        float4* o = (float4*)&out[gy * HW + gx];
        #pragma unroll
        for (int q = 0; q < 8; q++) {
            float4 fv;
            fv.x = (v >> (q * 4 + 0)) & 1u ? 1.0f : 0.0f;
            fv.y = (v >> (q * 4 + 1)) & 1u ? 1.0f : 0.0f;
            fv.z = (v >> (q * 4 + 2)) & 1u ? 1.0f : 0.0f;
            fv.w = (v >> (q * 4 + 3)) & 1u ? 1.0f : 0.0f;
            o[q] = fv;
        }
    }
}

// ---------------- launch ----------------
extern "C" void kernel_launch(void* const* d_in, const int* in_sizes, int n_in,
                              void* d_out, int out_size) {
    const float* x  = (const float*)d_in[0];
    const float* bk = (const float*)d_in[1];
    float* out = (float*)d_out;
    (void)in_sizes; (void)n_in; (void)out_size;

    int zn = NPATCH * (NCOARSE + 2);
    if (NPATCH * 2 * NSUB > zn) zn = NPATCH * 2 * NSUB;
    zero_k<<<(zn + 255) / 256, 256>>>();
    blur_hist<<<dim3(HW / 1024, HW / 32), 256>>>(x, bk);
    coarse_select<<<NPATCH, 1024>>>();
    refine_hist<<<NPATCH * 16, 256>>>();
    refine_select<<<NPATCH, 1024>>>();
    walk<<<1, 32>>>();
    close_k<<<dim3(HW / CTW, HW / CTH), 256>>>(out);
}